// round 1
// baseline (speedup 1.0000x reference)
#include <cuda_runtime.h>

#define HD 256
#define DO 128

// -------- device-global scratch (no allocations allowed) --------
__device__ float g_Wf[(64 + 128) * DO];   // folded W1@W2: user at 0, item at 64*DO
__device__ float g_bf[2 * DO];            // folded bias per type
__device__ float g_sum[2 * DO];           // per-column sum of h
__device__ float g_sumsq[2 * DO];         // per-column sum of h^2
__device__ float g_scale[2 * DO];         // BN+gamma folded scale
__device__ float g_shift[2 * DO];         // BN+beta folded shift

// -------- zero the stat accumulators (fresh each launch) --------
__global__ void zero_stats_kernel() {
    int t = threadIdx.x;
    if (t < 2 * DO) { g_sum[t] = 0.f; g_sumsq[t] = 0.f; }
}

// -------- fold W1@W2 and b1@W2+b2 (tiny) --------
__global__ void fold_kernel(const float* __restrict__ W1, const float* __restrict__ b1,
                            const float* __restrict__ W2, const float* __restrict__ b2,
                            int d_in, int type) {
    float* Wf = g_Wf + (type ? 64 * DO : 0);
    int row = blockIdx.x;
    int col = threadIdx.x;   // 128 threads
    float acc = 0.f;
    if (row < d_in) {
        const float* w1 = W1 + (size_t)row * HD;
        #pragma unroll 8
        for (int k = 0; k < HD; k++) acc = fmaf(w1[k], W2[k * DO + col], acc);
        Wf[row * DO + col] = acc;
    } else {
        #pragma unroll 8
        for (int k = 0; k < HD; k++) acc = fmaf(b1[k], W2[k * DO + col], acc);
        g_bf[type * DO + col] = acc + b2[col];
    }
}

// -------- main GEMM: h = X @ Wf + bf, write h to Hout, accumulate col stats --------
// BM=128, BN=128, BK=16, 256 threads, 8x8 microtile per thread.
template<int K, int TYPE>
__global__ __launch_bounds__(256, 2)
void gemm_stats_kernel(const float* __restrict__ X, float* __restrict__ Hout, int N) {
    __shared__ float Ws[16][128];
    __shared__ float Xs[16][132];     // +4 pad to break store bank conflicts
    __shared__ float ssum[128];
    __shared__ float ssq[128];

    const float* Wf = g_Wf + (TYPE ? 64 * DO : 0);
    const int tid = threadIdx.x;
    if (tid < 128) { ssum[tid] = 0.f; ssq[tid] = 0.f; }

    const int tx = tid & 15;          // col group: cols tx*8 .. tx*8+7
    const int ty = tid >> 4;          // row group: rows ty*8 .. ty*8+7
    const int rowBase = blockIdx.x << 7;

    float acc[8][8];
    #pragma unroll
    for (int i = 0; i < 8; i++)
        #pragma unroll
        for (int j = 0; j < 8; j++) acc[i][j] = 0.f;

    const int mload = tid >> 2;           // 0..63
    const int k4    = (tid & 3) << 2;     // 0,4,8,12

    for (int kb = 0; kb < K; kb += 16) {
        __syncthreads();
        // W tile: 16x128 contiguous
        {
            const float4* src = (const float4*)(Wf + kb * 128);
            float4* dst = (float4*)(&Ws[0][0]);
            dst[tid]       = src[tid];
            dst[tid + 256] = src[tid + 256];
        }
        // X tile: 128 rows x 16 cols, transposed into Xs[k][m]
        #pragma unroll
        for (int r = 0; r < 2; r++) {
            int mm = mload + r * 64;
            int grow = rowBase + mm;
            float4 v = make_float4(0.f, 0.f, 0.f, 0.f);
            if (grow < N) v = *(const float4*)(X + (size_t)grow * K + kb + k4);
            Xs[k4 + 0][mm] = v.x;
            Xs[k4 + 1][mm] = v.y;
            Xs[k4 + 2][mm] = v.z;
            Xs[k4 + 3][mm] = v.w;
        }
        __syncthreads();

        #pragma unroll
        for (int k = 0; k < 16; k++) {
            float a[8], b[8];
            *(float4*)&a[0] = *(const float4*)&Xs[k][ty * 8];
            *(float4*)&a[4] = *(const float4*)&Xs[k][ty * 8 + 4];
            *(float4*)&b[0] = *(const float4*)&Ws[k][tx * 8];
            *(float4*)&b[4] = *(const float4*)&Ws[k][tx * 8 + 4];
            #pragma unroll
            for (int i = 0; i < 8; i++)
                #pragma unroll
                for (int j = 0; j < 8; j++)
                    acc[i][j] = fmaf(a[i], b[j], acc[i][j]);
        }
    }

    // epilogue: bias, write h, per-thread column partial stats
    float bfr[8];
    #pragma unroll
    for (int j = 0; j < 8; j++) bfr[j] = g_bf[TYPE * DO + tx * 8 + j];

    float ps[8], pq[8];
    #pragma unroll
    for (int j = 0; j < 8; j++) { ps[j] = 0.f; pq[j] = 0.f; }

    #pragma unroll
    for (int i = 0; i < 8; i++) {
        int grow = rowBase + ty * 8 + i;
        if (grow < N) {
            float h[8];
            #pragma unroll
            for (int j = 0; j < 8; j++) {
                h[j] = acc[i][j] + bfr[j];
                ps[j] += h[j];
                pq[j] = fmaf(h[j], h[j], pq[j]);
            }
            *(float4*)(Hout + (size_t)grow * DO + tx * 8)     = make_float4(h[0], h[1], h[2], h[3]);
            *(float4*)(Hout + (size_t)grow * DO + tx * 8 + 4) = make_float4(h[4], h[5], h[6], h[7]);
        }
    }
    #pragma unroll
    for (int j = 0; j < 8; j++) {
        atomicAdd(&ssum[tx * 8 + j], ps[j]);
        atomicAdd(&ssq[tx * 8 + j],  pq[j]);
    }
    __syncthreads();
    if (tid < 128) {
        atomicAdd(&g_sum[TYPE * DO + tid],   ssum[tid]);
        atomicAdd(&g_sumsq[TYPE * DO + tid], ssq[tid]);
    }
}

// -------- fold BN stats + gamma/beta into per-column affine --------
__global__ void finalize_kernel(const float* __restrict__ gu, const float* __restrict__ bu,
                                const float* __restrict__ gi, const float* __restrict__ bi,
                                float invNu, float invNi) {
    int t = threadIdx.x;             // 0..255
    int type = t >> 7;
    int col  = t & 127;
    float invN = type ? invNi : invNu;
    float mean = g_sum[t] * invN;
    float var  = g_sumsq[t] * invN - mean * mean;
    float inv  = rsqrtf(var + 1e-5f);
    float gm = type ? gi[col] : gu[col];
    float bt = type ? bi[col] : bu[col];
    g_scale[t] = inv * gm;
    g_shift[t] = bt - mean * inv * gm;
}

// -------- in-place normalize + LeakyReLU, float4 --------
__global__ void norm_lrelu_kernel(float* __restrict__ out, long long userElems, long long total4) {
    __shared__ float sc[256], sh[256];
    int t = threadIdx.x;
    sc[t] = g_scale[t];
    sh[t] = g_shift[t];
    __syncthreads();

    long long i4 = (long long)blockIdx.x * 256 + t;
    if (i4 >= total4) return;
    long long i = i4 * 4;
    int base = (i < userElems) ? 0 : 128;
    int col  = (int)(i & 127);        // rows are 128 wide, 4-aligned

    float4 v = *(float4*)(out + i);
    float r[4] = {v.x, v.y, v.z, v.w};
    #pragma unroll
    for (int k = 0; k < 4; k++) {
        float h = fmaf(r[k], sc[base + col + k], sh[base + col + k]);
        r[k] = (h >= 0.f) ? h : 0.01f * h;
    }
    *(float4*)(out + i) = make_float4(r[0], r[1], r[2], r[3]);
}

extern "C" void kernel_launch(void* const* d_in, const int* in_sizes, int n_in,
                              void* d_out, int out_size) {
    const float* x_user  = (const float*)d_in[0];
    const float* x_item  = (const float*)d_in[1];
    const float* W1_user = (const float*)d_in[2];
    const float* b1_user = (const float*)d_in[3];
    const float* W1_item = (const float*)d_in[4];
    const float* b1_item = (const float*)d_in[5];
    const float* W2_user = (const float*)d_in[6];
    const float* b2_user = (const float*)d_in[7];
    const float* W2_item = (const float*)d_in[8];
    const float* b2_item = (const float*)d_in[9];
    const float* g_user  = (const float*)d_in[10];
    const float* be_user = (const float*)d_in[11];
    const float* g_item  = (const float*)d_in[12];
    const float* be_item = (const float*)d_in[13];

    const int Nu = in_sizes[0] / 64;
    const int Ni = in_sizes[1] / 128;
    float* out = (float*)d_out;

    zero_stats_kernel<<<1, 256>>>();
    fold_kernel<<<64 + 1, 128>>>(W1_user, b1_user, W2_user, b2_user, 64, 0);
    fold_kernel<<<128 + 1, 128>>>(W1_item, b1_item, W2_item, b2_item, 128, 1);

    gemm_stats_kernel<64, 0><<<(Nu + 127) / 128, 256>>>(x_user, out, Nu);
    gemm_stats_kernel<128, 1><<<(Ni + 127) / 128, 256>>>(x_item, out + (size_t)Nu * DO, Ni);

    finalize_kernel<<<1, 256>>>(g_user, be_user, g_item, be_item, 1.0f / (float)Nu, 1.0f / (float)Ni);

    long long total  = ((long long)Nu + (long long)Ni) * DO;
    long long total4 = total / 4;
    unsigned grid = (unsigned)((total4 + 255) / 256);
    norm_lrelu_kernel<<<grid, 256>>>(out, (long long)Nu * DO, total4);
}

// round 3
// speedup vs baseline: 1.3331x; 1.3331x over previous
#include <cuda_runtime.h>
#include <cuda_bf16.h>
#include <cstdint>

#define DO 128
#define HD 256

// ---------------- device-global scratch (no allocations allowed) ----------------
__device__ __nv_bfloat16 g_BT_hi[2][DO * 128];    // Wf^T split hi: [type][n*K + k]
__device__ __nv_bfloat16 g_BT_lo[2][DO * 128];    // Wf^T split lo
__device__ float g_sum[2 * DO];
__device__ float g_sumsq[2 * DO];
__device__ float g_scale[2 * DO];
__device__ float g_shift[2 * DO];

// ---------------- PTX helpers (arch-portable: ldmatrix + mma.sync) ----------------
__device__ __forceinline__ uint32_t smem_u32(const void* p) {
    uint32_t a;
    asm("{ .reg .u64 t; cvta.to.shared.u64 t, %1; cvt.u32.u64 %0, t; }" : "=r"(a) : "l"(p));
    return a;
}
__device__ __forceinline__ void ldsm4(uint32_t* r, uint32_t addr) {
    asm volatile("ldmatrix.sync.aligned.m8n8.x4.shared.b16 {%0,%1,%2,%3}, [%4];"
        : "=r"(r[0]), "=r"(r[1]), "=r"(r[2]), "=r"(r[3]) : "r"(addr));
}
__device__ __forceinline__ void ldsm2(uint32_t* r, uint32_t addr) {
    asm volatile("ldmatrix.sync.aligned.m8n8.x2.shared.b16 {%0,%1}, [%2];"
        : "=r"(r[0]), "=r"(r[1]) : "r"(addr));
}
__device__ __forceinline__ void mma16816(float* c, const uint32_t* a, const uint32_t* b) {
    asm volatile("mma.sync.aligned.m16n8k16.row.col.f32.bf16.bf16.f32 "
        "{%0,%1,%2,%3}, {%4,%5,%6,%7}, {%8,%9}, {%0,%1,%2,%3};"
        : "+f"(c[0]), "+f"(c[1]), "+f"(c[2]), "+f"(c[3])
        : "r"(a[0]), "r"(a[1]), "r"(a[2]), "r"(a[3]), "r"(b[0]), "r"(b[1]));
}

// ---------------- tiny kernels ----------------
__global__ void zero_stats_kernel() {
    int t = threadIdx.x;
    if (t < 2 * DO) { g_sum[t] = 0.f; g_sumsq[t] = 0.f; }
}

// fold: Wf = W1@W2 (K x 128); emit Wf^T as bf16 hi/lo pairs. (bias cancels in BN)
__global__ void fold_kernel(const float* __restrict__ W1, const float* __restrict__ W2,
                            int K, int type) {
    int n = blockIdx.x;      // output column 0..127
    int k = threadIdx.x;     // input dim
    if (k < K) {
        const float* w1 = W1 + (size_t)k * HD;
        float acc = 0.f;
        #pragma unroll 8
        for (int h = 0; h < HD; h++) acc = fmaf(w1[h], W2[h * DO + n], acc);
        __nv_bfloat16 hi = __float2bfloat16(acc);
        __nv_bfloat16 lo = __float2bfloat16(acc - __bfloat162float(hi));
        g_BT_hi[type][n * K + k] = hi;
        g_BT_lo[type][n * K + k] = lo;
    }
}

// ---------------- main GEMM + stats (mma.sync bf16 3-term split) ----------------
// Block tile 128x128, 8 warps (2 M x 4 N), warp tile 64x32.
// smem rows padded to 72 bf16 (144B) -> conflict-free ldmatrix.
template<int K, int TYPE>
__global__ __launch_bounds__(256, 2)
void mm_kernel(const float* __restrict__ X, float* __restrict__ Hout, int N, int ntiles) {
    constexpr int NCH    = K / 64;
    constexpr int CH     = 18432;               // 128 rows * 144B
    constexpr int SM_AHI = 0;
    constexpr int SM_ALO = CH;
    constexpr int SM_BHI = 2 * CH;
    constexpr int SM_BLO = 2 * CH + NCH * CH;
    constexpr int SM_STAT = 2 * CH + 2 * NCH * CH;

    extern __shared__ char smc[];
    const uint32_t sb = smem_u32(smc);
    float* ssum = (float*)(smc + SM_STAT);
    float* ssq  = (float*)(smc + SM_STAT + 512);

    const int tid  = threadIdx.x;
    const int wid  = tid >> 5;
    const int lane = tid & 31;
    const int wm   = wid >> 2;          // 0..1
    const int wn   = wid & 3;           // 0..3

    if (tid < 128) { ssum[tid] = 0.f; ssq[tid] = 0.f; }

    // ---- load B (Wf^T hi/lo) into smem once ----
    for (int i = tid; i < NCH * 1024; i += 256) {
        int c = i >> 10;
        int j = i & 1023;
        int n = j >> 3;
        int g = j & 7;
        const uint4* sh = (const uint4*)&g_BT_hi[TYPE][n * K + c * 64 + g * 8];
        const uint4* sl = (const uint4*)&g_BT_lo[TYPE][n * K + c * 64 + g * 8];
        *(uint4*)(smc + SM_BHI + c * CH + n * 144 + g * 16) = *sh;
        *(uint4*)(smc + SM_BLO + c * CH + n * 144 + g * 16) = *sl;
    }
    __syncthreads();

    // lane-dependent ldmatrix offsets
    const uint32_t aoff = (uint32_t)((lane & 15) * 144 + (lane >> 4) * 16);
    const int bl = lane & 15;
    const uint32_t boff = (uint32_t)((bl & 7) * 144 + ((bl >> 3) & 1) * 16);

    // running per-lane column stats
    float s[4][2], q[4][2];
    #pragma unroll
    for (int nt = 0; nt < 4; nt++) { s[nt][0] = s[nt][1] = 0.f; q[nt][0] = q[nt][1] = 0.f; }

    for (int tile = blockIdx.x; tile < ntiles; tile += gridDim.x) {
        const int rowBase = tile << 7;

        float acc[4][4][4];
        #pragma unroll
        for (int mt = 0; mt < 4; mt++)
            #pragma unroll
            for (int nt = 0; nt < 4; nt++)
                #pragma unroll
                for (int j = 0; j < 4; j++) acc[mt][nt][j] = 0.f;

        for (int c = 0; c < NCH; c++) {
            __syncthreads();   // protect A buffer from previous chunk's ldmatrix
            // ---- A chunk: 128 rows x 64 k fp32 -> bf16 hi/lo ----
            {
                const int row  = tid >> 1;
                const int kh   = (tid & 1) << 5;
                const int grow = rowBase + row;
                const bool valid = grow < N;
                const float* src = X + (size_t)grow * K + c * 64 + kh;
                #pragma unroll
                for (int g = 0; g < 4; g++) {
                    float4 v0 = make_float4(0.f, 0.f, 0.f, 0.f);
                    float4 v1 = v0;
                    if (valid) {
                        v0 = *(const float4*)(src + g * 8);
                        v1 = *(const float4*)(src + g * 8 + 4);
                    }
                    float f[8] = {v0.x, v0.y, v0.z, v0.w, v1.x, v1.y, v1.z, v1.w};
                    union { __nv_bfloat162 h2[4]; uint4 u; } Hi, Lo;
                    #pragma unroll
                    for (int j = 0; j < 4; j++) {
                        __nv_bfloat16 h0 = __float2bfloat16(f[2*j]);
                        __nv_bfloat16 h1 = __float2bfloat16(f[2*j+1]);
                        __nv_bfloat16 l0 = __float2bfloat16(f[2*j]   - __bfloat162float(h0));
                        __nv_bfloat16 l1 = __float2bfloat16(f[2*j+1] - __bfloat162float(h1));
                        Hi.h2[j] = __nv_bfloat162(h0, h1);
                        Lo.h2[j] = __nv_bfloat162(l0, l1);
                    }
                    uint32_t off = (uint32_t)(row * 144 + (kh + g * 8) * 2);
                    *(uint4*)(smc + SM_AHI + off) = Hi.u;
                    *(uint4*)(smc + SM_ALO + off) = Lo.u;
                }
            }
            __syncthreads();

            // ---- 3-term split MMA: AH*BH + AL*BH + AH*BL ----
            #pragma unroll
            for (int t = 0; t < 3; t++) {
                const uint32_t ab = sb + ((t == 1) ? SM_ALO : SM_AHI) + aoff + (uint32_t)(wm * 64 * 144);
                const uint32_t bb = sb + ((t == 2) ? SM_BLO : SM_BHI) + (uint32_t)(c * CH) + boff + (uint32_t)(wn * 32 * 144);
                #pragma unroll
                for (int ks = 0; ks < 4; ks++) {
                    uint32_t a[4][4], b[4][2];
                    #pragma unroll
                    for (int mt = 0; mt < 4; mt++) ldsm4(a[mt], ab + mt * 2304 + ks * 32);
                    #pragma unroll
                    for (int nt = 0; nt < 4; nt++) ldsm2(b[nt], bb + nt * 1152 + ks * 32);
                    #pragma unroll
                    for (int mt = 0; mt < 4; mt++)
                        #pragma unroll
                        for (int nt = 0; nt < 4; nt++) mma16816(acc[mt][nt], a[mt], b[nt]);
                }
            }
        }

        // ---- epilogue: store h (= x@Wf, no bias) + accumulate stats ----
        #pragma unroll
        for (int mt = 0; mt < 4; mt++) {
            const int r0 = rowBase + wm * 64 + mt * 16 + (lane >> 2);
            const int r1 = r0 + 8;
            const bool v0 = r0 < N, v1 = r1 < N;
            #pragma unroll
            for (int nt = 0; nt < 4; nt++) {
                const int col = wn * 32 + nt * 8 + (lane & 3) * 2;
                float h0 = acc[mt][nt][0], h1 = acc[mt][nt][1];
                float h2 = acc[mt][nt][2], h3 = acc[mt][nt][3];
                if (v0) {
                    *(float2*)(Hout + (size_t)r0 * DO + col) = make_float2(h0, h1);
                    s[nt][0] += h0; q[nt][0] = fmaf(h0, h0, q[nt][0]);
                    s[nt][1] += h1; q[nt][1] = fmaf(h1, h1, q[nt][1]);
                }
                if (v1) {
                    *(float2*)(Hout + (size_t)r1 * DO + col) = make_float2(h2, h3);
                    s[nt][0] += h2; q[nt][0] = fmaf(h2, h2, q[nt][0]);
                    s[nt][1] += h3; q[nt][1] = fmaf(h3, h3, q[nt][1]);
                }
            }
        }
    }

    // ---- flush stats: lane regs -> smem -> global (once per block) ----
    #pragma unroll
    for (int nt = 0; nt < 4; nt++) {
        const int col = wn * 32 + nt * 8 + (lane & 3) * 2;
        atomicAdd(&ssum[col],     s[nt][0]);
        atomicAdd(&ssq[col],      q[nt][0]);
        atomicAdd(&ssum[col + 1], s[nt][1]);
        atomicAdd(&ssq[col + 1],  q[nt][1]);
    }
    __syncthreads();
    if (tid < 128) {
        atomicAdd(&g_sum[TYPE * DO + tid],   ssum[tid]);
        atomicAdd(&g_sumsq[TYPE * DO + tid], ssq[tid]);
    }
}

// ---------------- BN fold + normalize ----------------
__global__ void finalize_kernel(const float* __restrict__ gu, const float* __restrict__ bu,
                                const float* __restrict__ gi, const float* __restrict__ bi,
                                float invNu, float invNi) {
    int t = threadIdx.x;
    int type = t >> 7;
    int col  = t & 127;
    float invN = type ? invNi : invNu;
    float mean = g_sum[t] * invN;
    float var  = g_sumsq[t] * invN - mean * mean;
    float inv  = rsqrtf(var + 1e-5f);
    float gm = type ? gi[col] : gu[col];
    float bt = type ? bi[col] : bu[col];
    g_scale[t] = inv * gm;
    g_shift[t] = bt - mean * inv * gm;
}

__global__ void norm_lrelu_kernel(float* __restrict__ out, long long userElems, long long total4) {
    __shared__ float sc[256], sh[256];
    int t = threadIdx.x;
    sc[t] = g_scale[t];
    sh[t] = g_shift[t];
    __syncthreads();

    long long i4 = (long long)blockIdx.x * 256 + t;
    if (i4 >= total4) return;
    long long i = i4 * 4;
    int base = (i < userElems) ? 0 : 128;
    int col  = (int)(i & 127);

    float4 v = *(float4*)(out + i);
    float r[4] = {v.x, v.y, v.z, v.w};
    #pragma unroll
    for (int k = 0; k < 4; k++) {
        float h = fmaf(r[k], sc[base + col + k], sh[base + col + k]);
        r[k] = (h >= 0.f) ? h : 0.01f * h;
    }
    *(float4*)(out + i) = make_float4(r[0], r[1], r[2], r[3]);
}

// ---------------- launch ----------------
extern "C" void kernel_launch(void* const* d_in, const int* in_sizes, int n_in,
                              void* d_out, int out_size) {
    const float* x_user  = (const float*)d_in[0];
    const float* x_item  = (const float*)d_in[1];
    const float* W1_user = (const float*)d_in[2];
    const float* W1_item = (const float*)d_in[4];
    const float* W2_user = (const float*)d_in[6];
    const float* W2_item = (const float*)d_in[8];
    const float* g_user  = (const float*)d_in[10];
    const float* be_user = (const float*)d_in[11];
    const float* g_item  = (const float*)d_in[12];
    const float* be_item = (const float*)d_in[13];

    const int Nu = in_sizes[0] / 64;
    const int Ni = in_sizes[1] / 128;
    float* out = (float*)d_out;

    constexpr int SMEM_U = 2 * 18432 + 2 * 1 * 18432 + 1024;  // 74752
    constexpr int SMEM_I = 2 * 18432 + 2 * 2 * 18432 + 1024;  // 111616
    cudaFuncSetAttribute(mm_kernel<64, 0>,  cudaFuncAttributeMaxDynamicSharedMemorySize, SMEM_U);
    cudaFuncSetAttribute(mm_kernel<128, 1>, cudaFuncAttributeMaxDynamicSharedMemorySize, SMEM_I);

    zero_stats_kernel<<<1, 256>>>();
    fold_kernel<<<DO, 128>>>(W1_user, W2_user, 64, 0);
    fold_kernel<<<DO, 128>>>(W1_item, W2_item, 128, 1);

    const int tiles_u = (Nu + 127) / 128;
    const int tiles_i = (Ni + 127) / 128;
    const int grid_u = tiles_u < 592 ? tiles_u : 592;
    const int grid_i = tiles_i < 592 ? tiles_i : 592;

    mm_kernel<64, 0><<<grid_u, 256, SMEM_U>>>(x_user, out, Nu, tiles_u);
    mm_kernel<128, 1><<<grid_i, 256, SMEM_I>>>(x_item, out + (size_t)Nu * DO, Ni, tiles_i);

    finalize_kernel<<<1, 256>>>(g_user, be_user, g_item, be_item, 1.0f / (float)Nu, 1.0f / (float)Ni);

    long long total  = ((long long)Nu + (long long)Ni) * DO;
    long long total4 = total / 4;
    unsigned grid = (unsigned)((total4 + 255) / 256);
    norm_lrelu_kernel<<<grid, 256>>>(out, (long long)Nu * DO, total4);
}

// round 4
// speedup vs baseline: 1.7014x; 1.2763x over previous
#include <cuda_runtime.h>
#include <cuda_bf16.h>
#include <cstdint>

#define DO 128
#define HD 256

// ---------------- device-global scratch ----------------
__device__ __align__(16) __nv_bfloat16 g_BT_hi[2][DO * 128];  // Wf^T hi [type][n*K+k]
__device__ __align__(16) __nv_bfloat16 g_BT_lo[2][DO * 128];  // Wf^T lo
__device__ float g_sum[2 * DO];
__device__ float g_sumsq[2 * DO];
__device__ float g_scale[2 * DO];
__device__ float g_shift[2 * DO];

// ---------------- PTX helpers ----------------
__device__ __forceinline__ uint32_t smem_u32(const void* p) {
    uint32_t a;
    asm("{ .reg .u64 t; cvta.to.shared.u64 t, %1; cvt.u32.u64 %0, t; }" : "=r"(a) : "l"(p));
    return a;
}
__device__ __forceinline__ void ldsm4(uint32_t* r, uint32_t addr) {
    asm volatile("ldmatrix.sync.aligned.m8n8.x4.shared.b16 {%0,%1,%2,%3}, [%4];"
        : "=r"(r[0]), "=r"(r[1]), "=r"(r[2]), "=r"(r[3]) : "r"(addr));
}
__device__ __forceinline__ void ldsm2(uint32_t* r, uint32_t addr) {
    asm volatile("ldmatrix.sync.aligned.m8n8.x2.shared.b16 {%0,%1}, [%2];"
        : "=r"(r[0]), "=r"(r[1]) : "r"(addr));
}
__device__ __forceinline__ void mma16816(float* c, const uint32_t* a, const uint32_t* b) {
    asm volatile("mma.sync.aligned.m16n8k16.row.col.f32.bf16.bf16.f32 "
        "{%0,%1,%2,%3}, {%4,%5,%6,%7}, {%8,%9}, {%0,%1,%2,%3};"
        : "+f"(c[0]), "+f"(c[1]), "+f"(c[2]), "+f"(c[3])
        : "r"(a[0]), "r"(a[1]), "r"(a[2]), "r"(a[3]), "r"(b[0]), "r"(b[1]));
}
// pack two f32 -> bf16x2 (lo element in low half)
__device__ __forceinline__ uint32_t pk(float lo, float hi) {
    uint32_t r;
    asm("cvt.rn.bf16x2.f32 %0, %1, %2;" : "=r"(r) : "f"(hi), "f"(lo));
    return r;
}
__device__ __forceinline__ float bfres(float a) {   // a - bf16(a)
    return a - __bfloat162float(__float2bfloat16(a));
}

// ---------------- tiny kernels ----------------
__global__ void zero_stats_kernel() {
    int t = threadIdx.x;
    if (t < 2 * DO) { g_sum[t] = 0.f; g_sumsq[t] = 0.f; }
}

// fold Wf = W1@W2; emit Wf^T bf16 hi/lo (bias cancels in BN)
__global__ void fold_kernel(const float* __restrict__ W1, const float* __restrict__ W2,
                            int K, int type) {
    int n = blockIdx.x;
    int k = threadIdx.x;
    if (k < K) {
        const float* w1 = W1 + (size_t)k * HD;
        float acc = 0.f;
        #pragma unroll 8
        for (int h = 0; h < HD; h++) acc = fmaf(w1[h], W2[h * DO + n], acc);
        __nv_bfloat16 hi = __float2bfloat16(acc);
        g_BT_hi[type][n * K + k] = hi;
        g_BT_lo[type][n * K + k] = __float2bfloat16(acc - __bfloat162float(hi));
    }
}

// ---------------- pass 1: stats GEMM (1-term bf16, no output write) ----------------
// 8 warps as 2(M) x 4(N); warp tile 64x32; A direct from global to fragments.
template<int K, int TYPE>
__global__ __launch_bounds__(256, 2)
void stats_kernel(const float* __restrict__ X, int N, int ntiles) {
    constexpr int STR = K * 2 + 16;            // B smem row stride (bytes)
    constexpr int SM_B = 0;
    constexpr int SM_STAT = 128 * STR;

    extern __shared__ char smc[];
    const uint32_t sb = smem_u32(smc);
    float* ssum = (float*)(smc + SM_STAT);
    float* ssq  = (float*)(smc + SM_STAT + 512);

    const int tid = threadIdx.x;
    const int lane = tid & 31;
    const int wid = tid >> 5;
    const int wm = wid >> 2, wn = wid & 3;

    // B hi -> smem (once)
    for (int i = tid; i < 128 * (K / 8); i += 256) {
        int n = i / (K / 8), g = i % (K / 8);
        *(uint4*)(smc + SM_B + n * STR + g * 16) = *(const uint4*)&g_BT_hi[TYPE][n * K + g * 8];
    }
    if (tid < 128) { ssum[tid] = 0.f; ssq[tid] = 0.f; }
    __syncthreads();

    const int bl = lane & 15;
    const uint32_t bb = sb + SM_B + (uint32_t)((wn * 32 + (bl & 7)) * STR + ((bl >> 3) & 1) * 16);

    float s[4][2], q[4][2];
    #pragma unroll
    for (int nt = 0; nt < 4; nt++) { s[nt][0] = s[nt][1] = 0.f; q[nt][0] = q[nt][1] = 0.f; }

    const int rA = wm * 64 + (lane >> 2);
    const int cA = (lane & 3) * 2;

    for (int tile = blockIdx.x; tile < ntiles; tile += gridDim.x) {
        const int tb = tile << 7;
        float acc[4][4][4];
        #pragma unroll
        for (int mt = 0; mt < 4; mt++)
            #pragma unroll
            for (int nt = 0; nt < 4; nt++)
                #pragma unroll
                for (int j = 0; j < 4; j++) acc[mt][nt][j] = 0.f;

        #pragma unroll
        for (int ks = 0; ks < K / 16; ks++) {
            uint32_t A[4][4];
            #pragma unroll
            for (int mt = 0; mt < 4; mt++) {
                int r0 = tb + rA + mt * 16, r1 = r0 + 8;
                const float* p0 = X + (size_t)r0 * K + ks * 16 + cA;
                const float* p1 = X + (size_t)r1 * K + ks * 16 + cA;
                float2 z = make_float2(0.f, 0.f);
                float2 f00 = (r0 < N) ? *(const float2*)p0       : z;
                float2 f01 = (r0 < N) ? *(const float2*)(p0 + 8) : z;
                float2 f10 = (r1 < N) ? *(const float2*)p1       : z;
                float2 f11 = (r1 < N) ? *(const float2*)(p1 + 8) : z;
                A[mt][0] = pk(f00.x, f00.y);
                A[mt][1] = pk(f10.x, f10.y);
                A[mt][2] = pk(f01.x, f01.y);
                A[mt][3] = pk(f11.x, f11.y);
            }
            uint32_t b[4][2];
            #pragma unroll
            for (int nt = 0; nt < 4; nt++) ldsm2(b[nt], bb + nt * 8 * STR + ks * 32);
            #pragma unroll
            for (int mt = 0; mt < 4; mt++)
                #pragma unroll
                for (int nt = 0; nt < 4; nt++) mma16816(acc[mt][nt], A[mt], b[nt]);
        }
        // stats (invalid rows contributed zeros -> harmless)
        #pragma unroll
        for (int mt = 0; mt < 4; mt++)
            #pragma unroll
            for (int nt = 0; nt < 4; nt++) {
                float c0 = acc[mt][nt][0], c1 = acc[mt][nt][1];
                float c2 = acc[mt][nt][2], c3 = acc[mt][nt][3];
                s[nt][0] += c0 + c2; q[nt][0] = fmaf(c0, c0, fmaf(c2, c2, q[nt][0]));
                s[nt][1] += c1 + c3; q[nt][1] = fmaf(c1, c1, fmaf(c3, c3, q[nt][1]));
            }
    }

    #pragma unroll
    for (int nt = 0; nt < 4; nt++) {
        int col = wn * 32 + nt * 8 + (lane & 3) * 2;
        atomicAdd(&ssum[col],     s[nt][0]);
        atomicAdd(&ssq[col],      q[nt][0]);
        atomicAdd(&ssum[col + 1], s[nt][1]);
        atomicAdd(&ssq[col + 1],  q[nt][1]);
    }
    __syncthreads();
    if (tid < 128) {
        atomicAdd(&g_sum[TYPE * DO + tid],   ssum[tid]);
        atomicAdd(&g_sumsq[TYPE * DO + tid], ssq[tid]);
    }
}

// ---------------- finalize: fold BN + gamma/beta into affine ----------------
__global__ void finalize_kernel(const float* __restrict__ gu, const float* __restrict__ bu,
                                const float* __restrict__ gi, const float* __restrict__ bi,
                                float invNu, float invNi) {
    int t = threadIdx.x;
    int type = t >> 7, col = t & 127;
    float invN = type ? invNi : invNu;
    float mean = g_sum[t] * invN;
    float var  = g_sumsq[t] * invN - mean * mean;
    float inv  = rsqrtf(var + 1e-5f);
    float gm = type ? gi[col] : gu[col];
    float bt = type ? bi[col] : bu[col];
    g_scale[t] = inv * gm;
    g_shift[t] = bt - mean * inv * gm;
}

// ---------------- pass 2: output GEMM (3-term bf16) + norm + LeakyReLU ----------------
// 8 warps x (16 rows x 128 cols) -> zero A redundancy, no mainloop barriers.
template<int K, int TYPE>
__global__ __launch_bounds__(256, 2)
void out_kernel(const float* __restrict__ X, float* __restrict__ Out, int N, int ntiles) {
    constexpr int STR = K * 2 + 16;
    constexpr int SM_BH = 0;
    constexpr int SM_BL = 128 * STR;
    constexpr int SM_SC = 2 * 128 * STR;
    constexpr int SM_SH = SM_SC + 512;

    extern __shared__ char smc[];
    const uint32_t sb = smem_u32(smc);
    const int tid = threadIdx.x;
    const int lane = tid & 31;
    const int wid = tid >> 5;

    for (int i = tid; i < 128 * (K / 8); i += 256) {
        int n = i / (K / 8), g = i % (K / 8);
        *(uint4*)(smc + SM_BH + n * STR + g * 16) = *(const uint4*)&g_BT_hi[TYPE][n * K + g * 8];
        *(uint4*)(smc + SM_BL + n * STR + g * 16) = *(const uint4*)&g_BT_lo[TYPE][n * K + g * 8];
    }
    if (tid < 128) {
        ((float*)(smc + SM_SC))[tid] = g_scale[TYPE * DO + tid];
        ((float*)(smc + SM_SH))[tid] = g_shift[TYPE * DO + tid];
    }
    __syncthreads();

    const uint32_t bb4 = (uint32_t)(((lane & 7) + ((lane >> 4) & 1) * 8) * STR + ((lane >> 3) & 1) * 16);
    const int rA = wid * 16 + (lane >> 2);
    const int cA = (lane & 3) * 2;
    const float* scp = (const float*)(smc + SM_SC);
    const float* shp = (const float*)(smc + SM_SH);

    for (int tile = blockIdx.x; tile < ntiles; tile += gridDim.x) {
        const int tb = tile << 7;
        const int r0 = tb + rA, r1 = r0 + 8;
        const bool v0 = r0 < N, v1 = r1 < N;

        float acc[16][4];
        #pragma unroll
        for (int nt = 0; nt < 16; nt++)
            #pragma unroll
            for (int j = 0; j < 4; j++) acc[nt][j] = 0.f;

        #pragma unroll
        for (int ks = 0; ks < K / 16; ks++) {
            const float* p0 = X + (size_t)r0 * K + ks * 16 + cA;
            const float* p1 = X + (size_t)r1 * K + ks * 16 + cA;
            float2 z = make_float2(0.f, 0.f);
            float2 f00 = v0 ? *(const float2*)p0       : z;
            float2 f01 = v0 ? *(const float2*)(p0 + 8) : z;
            float2 f10 = v1 ? *(const float2*)p1       : z;
            float2 f11 = v1 ? *(const float2*)(p1 + 8) : z;

            uint32_t AH[4], AL[4];
            AH[0] = pk(f00.x, f00.y); AL[0] = pk(bfres(f00.x), bfres(f00.y));
            AH[1] = pk(f10.x, f10.y); AL[1] = pk(bfres(f10.x), bfres(f10.y));
            AH[2] = pk(f01.x, f01.y); AL[2] = pk(bfres(f01.x), bfres(f01.y));
            AH[3] = pk(f11.x, f11.y); AL[3] = pk(bfres(f11.x), bfres(f11.y));

            #pragma unroll
            for (int p = 0; p < 8; p++) {
                uint32_t bh[4], blr[4];
                ldsm4(bh,  sb + SM_BH + bb4 + (uint32_t)(p * 16 * STR + ks * 32));
                ldsm4(blr, sb + SM_BL + bb4 + (uint32_t)(p * 16 * STR + ks * 32));
                mma16816(acc[2*p],     AH, &bh[0]);
                mma16816(acc[2*p],     AL, &bh[0]);
                mma16816(acc[2*p],     AH, &blr[0]);
                mma16816(acc[2*p + 1], AH, &bh[2]);
                mma16816(acc[2*p + 1], AL, &bh[2]);
                mma16816(acc[2*p + 1], AH, &blr[2]);
            }
        }

        // epilogue: normalize + LeakyReLU + store
        #pragma unroll
        for (int nt = 0; nt < 16; nt++) {
            int c = nt * 8 + cA;
            float2 sc2 = *(const float2*)(scp + c);
            float2 sh2 = *(const float2*)(shp + c);
            if (v0) {
                float o0 = fmaf(acc[nt][0], sc2.x, sh2.x);
                float o1 = fmaf(acc[nt][1], sc2.y, sh2.y);
                o0 = (o0 >= 0.f) ? o0 : 0.01f * o0;
                o1 = (o1 >= 0.f) ? o1 : 0.01f * o1;
                *(float2*)(Out + (size_t)r0 * DO + c) = make_float2(o0, o1);
            }
            if (v1) {
                float o2 = fmaf(acc[nt][2], sc2.x, sh2.x);
                float o3 = fmaf(acc[nt][3], sc2.y, sh2.y);
                o2 = (o2 >= 0.f) ? o2 : 0.01f * o2;
                o3 = (o3 >= 0.f) ? o3 : 0.01f * o3;
                *(float2*)(Out + (size_t)r1 * DO + c) = make_float2(o2, o3);
            }
        }
    }
}

// ---------------- launch ----------------
extern "C" void kernel_launch(void* const* d_in, const int* in_sizes, int n_in,
                              void* d_out, int out_size) {
    const float* x_user  = (const float*)d_in[0];
    const float* x_item  = (const float*)d_in[1];
    const float* W1_user = (const float*)d_in[2];
    const float* W1_item = (const float*)d_in[4];
    const float* W2_user = (const float*)d_in[6];
    const float* W2_item = (const float*)d_in[8];
    const float* g_user  = (const float*)d_in[10];
    const float* be_user = (const float*)d_in[11];
    const float* g_item  = (const float*)d_in[12];
    const float* be_item = (const float*)d_in[13];

    const int Nu = in_sizes[0] / 64;
    const int Ni = in_sizes[1] / 128;
    float* out = (float*)d_out;

    constexpr int STAT_SM_U = 128 * (64 * 2 + 16) + 1024;        // 19456
    constexpr int STAT_SM_I = 128 * (128 * 2 + 16) + 1024;       // 35840
    constexpr int OUT_SM_U  = 2 * 128 * (64 * 2 + 16) + 1024;    // 37888
    constexpr int OUT_SM_I  = 2 * 128 * (128 * 2 + 16) + 1024;   // 70656
    cudaFuncSetAttribute(stats_kernel<64, 0>,  cudaFuncAttributeMaxDynamicSharedMemorySize, STAT_SM_U);
    cudaFuncSetAttribute(stats_kernel<128, 1>, cudaFuncAttributeMaxDynamicSharedMemorySize, STAT_SM_I);
    cudaFuncSetAttribute(out_kernel<64, 0>,    cudaFuncAttributeMaxDynamicSharedMemorySize, OUT_SM_U);
    cudaFuncSetAttribute(out_kernel<128, 1>,   cudaFuncAttributeMaxDynamicSharedMemorySize, OUT_SM_I);

    zero_stats_kernel<<<1, 256>>>();
    fold_kernel<<<DO, 128>>>(W1_user, W2_user, 64, 0);
    fold_kernel<<<DO, 128>>>(W1_item, W2_item, 128, 1);

    const int tiles_u = (Nu + 127) / 128;
    const int tiles_i = (Ni + 127) / 128;
    const int GRID = 592;

    stats_kernel<64, 0><<<(tiles_u < GRID ? tiles_u : GRID), 256, STAT_SM_U>>>(x_user, Nu, tiles_u);
    stats_kernel<128, 1><<<(tiles_i < GRID ? tiles_i : GRID), 256, STAT_SM_I>>>(x_item, Ni, tiles_i);

    finalize_kernel<<<1, 256>>>(g_user, be_user, g_item, be_item, 1.0f / (float)Nu, 1.0f / (float)Ni);

    out_kernel<64, 0><<<(tiles_u < GRID ? tiles_u : GRID), 256, OUT_SM_U>>>(x_user, out, Nu, tiles_u);
    out_kernel<128, 1><<<(tiles_i < GRID ? tiles_i : GRID), 256, OUT_SM_I>>>(x_item, out + (size_t)Nu * DO, Ni, tiles_i);
}

// round 5
// speedup vs baseline: 2.6939x; 1.5834x over previous
#include <cuda_runtime.h>
#include <cuda_fp16.h>
#include <cstdint>

#define DO 128
#define HD 256

// ---------------- device-global scratch ----------------
__device__ __align__(16) __half g_Bh[2][DO * 128];     // fp16(Wf^T) [type][n*K + k]
__device__ float g_sum[2 * DO];
__device__ float g_sumsq[2 * DO];
__device__ float g_scale[2 * DO];
__device__ float g_shift[2 * DO];
__device__ __align__(16) __half g_H[128000000ULL];     // h fp16 (1e6 rows x 128)

// ---------------- PTX helpers ----------------
__device__ __forceinline__ uint32_t smem_u32(const void* p) {
    uint32_t a;
    asm("{ .reg .u64 t; cvta.to.shared.u64 t, %1; cvt.u32.u64 %0, t; }" : "=r"(a) : "l"(p));
    return a;
}
__device__ __forceinline__ void ldsm4(uint32_t* r, uint32_t addr) {
    asm volatile("ldmatrix.sync.aligned.m8n8.x4.shared.b16 {%0,%1,%2,%3}, [%4];"
        : "=r"(r[0]), "=r"(r[1]), "=r"(r[2]), "=r"(r[3]) : "r"(addr));
}
__device__ __forceinline__ void mmah(float* c, const uint32_t* a, const uint32_t* b) {
    asm volatile("mma.sync.aligned.m16n8k16.row.col.f32.f16.f16.f32 "
        "{%0,%1,%2,%3}, {%4,%5,%6,%7}, {%8,%9}, {%0,%1,%2,%3};"
        : "+f"(c[0]), "+f"(c[1]), "+f"(c[2]), "+f"(c[3])
        : "r"(a[0]), "r"(a[1]), "r"(a[2]), "r"(a[3]), "r"(b[0]), "r"(b[1]));
}
// pack (lo, hi) -> f16x2 with lo in low half
__device__ __forceinline__ uint32_t pkh(float lo, float hi) {
    uint32_t r;
    asm("cvt.rn.f16x2.f32 %0, %1, %2;" : "=r"(r) : "f"(hi), "f"(lo));
    return r;
}
__device__ __forceinline__ float hres(float a) {   // a - fp16(a)
    return a - __half2float(__float2half_rn(a));
}
__device__ __forceinline__ void cp16(uint32_t dst, const float* src, bool v) {
    int sz = v ? 16 : 0;
    asm volatile("cp.async.cg.shared.global [%0], [%1], 16, %2;"
                 :: "r"(dst), "l"(src), "r"(sz) : "memory");
}
#define CP_COMMIT() asm volatile("cp.async.commit_group;" ::: "memory")
#define CP_WAIT0()  asm volatile("cp.async.wait_group 0;" ::: "memory")

// ---------------- tiny kernels ----------------
__global__ void zero_stats_kernel() {
    int t = threadIdx.x;
    if (t < 2 * DO) { g_sum[t] = 0.f; g_sumsq[t] = 0.f; }
}

// fold Wf = W1@W2 -> fp16(Wf^T)  (bias cancels in BN)
__global__ void fold_kernel(const float* __restrict__ W1, const float* __restrict__ W2,
                            int K, int type) {
    int n = blockIdx.x;
    int k = threadIdx.x;
    if (k < K) {
        const float* w1 = W1 + (size_t)k * HD;
        float acc = 0.f;
        #pragma unroll 8
        for (int h = 0; h < HD; h++) acc = fmaf(w1[h], W2[h * DO + n], acc);
        g_Bh[type][n * K + k] = __float2half_rn(acc);
    }
}

// ---------------- pass 1: GEMM (2-term fp16), h -> g_H (fp16), column stats ----------------
// 256 thr / 8 warps; tile 128 rows; warp = 16 rows x 128 cols.
// A: cp.async double-buffered fp32 smem, XOR swizzle; chunk = 64 k.
template<int K, int TYPE>
__global__ __launch_bounds__(256, 2)
void gemm1_kernel(const float* __restrict__ X, __half* __restrict__ H, int N, int ntiles) {
    constexpr int NCH  = K / 64;
    constexpr int STR2 = K * 2 + 16;                 // B row stride (bytes)
    constexpr int SM_B    = 65536;                   // after two 32KB A buffers
    constexpr int SM_STAT = SM_B + 128 * STR2;

    extern __shared__ char smc[];
    const uint32_t sb = smem_u32(smc);
    float* ssum = (float*)(smc + SM_STAT);
    float* ssq  = (float*)(smc + SM_STAT + 512);

    const int tid  = threadIdx.x;
    const int lane = tid & 31;
    const int wid  = tid >> 5;
    const int jj   = lane & 3;
    const int rA   = wid * 16 + (lane >> 2);         // warp-private rows rA, rA+8
    const uint32_t sw0 = (uint32_t)((lane >> 2) << 4);
    const uint32_t sw1 = sw0 ^ 128u;

    // B -> smem once
    for (int i = tid; i < 128 * (K / 8); i += 256) {
        int n = i / (K / 8), g = i % (K / 8);
        *(uint4*)(smc + SM_B + n * STR2 + g * 16) = *(const uint4*)&g_Bh[TYPE][n * K + g * 8];
    }
    if (tid < 128) { ssum[tid] = 0.f; ssq[tid] = 0.f; }
    __syncthreads();

    const uint32_t bb4 = (uint32_t)(((lane & 7) + ((lane >> 4) & 1) * 8) * STR2 + ((lane >> 3) & 1) * 16);

    float s8[8], q8[8];
    #pragma unroll
    for (int k = 0; k < 8; k++) { s8[k] = 0.f; q8[k] = 0.f; }

    // prefetch helper (lambda-ish via macro-free inline)
    auto prefetch = [&](int tile, int c, int buf) {
        const uint32_t ab = sb + buf * 32768;
        const int koff = c * 64;
        #pragma unroll
        for (int r8 = 0; r8 < 8; r8++) {
            int i   = tid + r8 * 256;
            int row = i >> 4;
            int cb  = (i & 15) << 4;
            int grow = (tile << 7) + row;
            bool v = grow < N;
            const float* src = v ? (X + (size_t)grow * K + koff + (cb >> 2)) : X;
            cp16(ab + (uint32_t)(row * 256) + ((uint32_t)cb ^ (uint32_t)((row & 15) << 4)), src, v);
        }
    };

    int tile0 = blockIdx.x;
    if (tile0 < ntiles) prefetch(tile0, 0, 0);
    CP_COMMIT();
    int buf = 0;

    for (int tile = tile0; tile < ntiles; tile += gridDim.x) {
        float acc[16][4];
        #pragma unroll
        for (int nt = 0; nt < 16; nt++)
            #pragma unroll
            for (int j = 0; j < 4; j++) acc[nt][j] = 0.f;

        #pragma unroll
        for (int c = 0; c < NCH; c++) {
            CP_WAIT0();
            __syncthreads();
            // issue next prefetch
            {
                int nc = c + 1, nt2 = tile;
                if (nc == NCH) { nc = 0; nt2 = tile + gridDim.x; }
                if (nt2 < ntiles) prefetch(nt2, nc, buf ^ 1);
                CP_COMMIT();
            }
            const int abuf = buf * 32768;
            #pragma unroll
            for (int ks = 0; ks < 4; ks++) {
                const uint32_t cb = (uint32_t)(ks * 64 + jj * 8);
                float2 x00 = *(const float2*)(smc + abuf + rA * 256 + (cb ^ sw0));
                float2 x10 = *(const float2*)(smc + abuf + (rA + 8) * 256 + (cb ^ sw1));
                float2 x01 = *(const float2*)(smc + abuf + rA * 256 + ((cb + 32) ^ sw0));
                float2 x11 = *(const float2*)(smc + abuf + (rA + 8) * 256 + ((cb + 32) ^ sw1));

                uint32_t AH[4], AL[4];
                AH[0] = pkh(x00.x, x00.y); AL[0] = pkh(hres(x00.x), hres(x00.y));
                AH[1] = pkh(x10.x, x10.y); AL[1] = pkh(hres(x10.x), hres(x10.y));
                AH[2] = pkh(x01.x, x01.y); AL[2] = pkh(hres(x01.x), hres(x01.y));
                AH[3] = pkh(x11.x, x11.y); AL[3] = pkh(hres(x11.x), hres(x11.y));

                const uint32_t bbase = sb + SM_B + bb4 + (uint32_t)((c * 4 + ks) * 32);
                #pragma unroll
                for (int p = 0; p < 8; p++) {
                    uint32_t bh[4];
                    ldsm4(bh, bbase + (uint32_t)(p * 16 * STR2));
                    mmah(acc[2 * p],     AH, &bh[0]);
                    mmah(acc[2 * p],     AL, &bh[0]);
                    mmah(acc[2 * p + 1], AH, &bh[2]);
                    mmah(acc[2 * p + 1], AL, &bh[2]);
                }
            }
            buf ^= 1;
        }

        // ---- epilogue: warp-private staging in the just-consumed buffer ----
        const int stb = (buf ^ 1) * 32768;
        #pragma unroll
        for (int nt = 0; nt < 16; nt++) {
            uint32_t c2 = (uint32_t)(nt * 16 + jj * 4);
            *(uint32_t*)(smc + stb + rA * 256 + (c2 ^ sw0))       = pkh(acc[nt][0], acc[nt][1]);
            *(uint32_t*)(smc + stb + (rA + 8) * 256 + (c2 ^ sw1)) = pkh(acc[nt][2], acc[nt][3]);
        }
        __syncwarp();
        #pragma unroll
        for (int i = 0; i < 8; i++) {
            int rr = wid * 16 + (lane >> 4) + i * 2;
            uint32_t c2 = (uint32_t)((lane & 15) << 4);
            uint4 v = *(const uint4*)(smc + stb + rr * 256 + (c2 ^ (uint32_t)((rr & 15) << 4)));
            const __half2* hv = (const __half2*)&v;
            #pragma unroll
            for (int k = 0; k < 4; k++) {
                float2 f = __half22float2(hv[k]);
                s8[2 * k]     += f.x;  q8[2 * k]     = fmaf(f.x, f.x, q8[2 * k]);
                s8[2 * k + 1] += f.y;  q8[2 * k + 1] = fmaf(f.y, f.y, q8[2 * k + 1]);
            }
            int grow = (tile << 7) + rr;
            if (grow < N) *(uint4*)(H + (size_t)grow * DO + (lane & 15) * 8) = v;
        }
    }

    // ---- flush stats ----
    #pragma unroll
    for (int k = 0; k < 8; k++) {
        s8[k] += __shfl_down_sync(0xFFFFFFFFu, s8[k], 16);
        q8[k] += __shfl_down_sync(0xFFFFFFFFu, q8[k], 16);
    }
    if (lane < 16) {
        #pragma unroll
        for (int k = 0; k < 8; k++) {
            atomicAdd(&ssum[lane * 8 + k], s8[k]);
            atomicAdd(&ssq[lane * 8 + k],  q8[k]);
        }
    }
    __syncthreads();
    if (tid < 128) {
        atomicAdd(&g_sum[TYPE * DO + tid],   ssum[tid]);
        atomicAdd(&g_sumsq[TYPE * DO + tid], ssq[tid]);
    }
}

// ---------------- finalize: fold BN + gamma/beta into affine ----------------
__global__ void finalize_kernel(const float* __restrict__ gu, const float* __restrict__ bu,
                                const float* __restrict__ gi, const float* __restrict__ bi,
                                float invNu, float invNi) {
    int t = threadIdx.x;
    int type = t >> 7, col = t & 127;
    float invN = type ? invNi : invNu;
    float mean = g_sum[t] * invN;
    float var  = g_sumsq[t] * invN - mean * mean;
    float inv  = rsqrtf(var + 1e-5f);
    float gm = type ? gi[col] : gu[col];
    float bt = type ? bi[col] : bu[col];
    g_scale[t] = inv * gm;
    g_shift[t] = bt - mean * inv * gm;
}

// ---------------- pass 2: normalize + LeakyReLU (fp16 h -> fp32 out) ----------------
__global__ void norm_kernel(const __half* __restrict__ H, float* __restrict__ out,
                            long long userElems, long long total4) {
    __shared__ float sc[256], sh[256];
    int t = threadIdx.x;
    sc[t] = g_scale[t];
    sh[t] = g_shift[t];
    __syncthreads();

    long long i4 = (long long)blockIdx.x * 256 + t;
    if (i4 >= total4) return;
    long long i = i4 * 4;
    int base = (i < userElems) ? 0 : 128;
    int col  = (int)(i & 127);

    uint2 hv = *(const uint2*)(H + i);
    float2 f0 = __half22float2(*(const __half2*)&hv.x);
    float2 f1 = __half22float2(*(const __half2*)&hv.y);
    float r[4] = {f0.x, f0.y, f1.x, f1.y};
    #pragma unroll
    for (int k = 0; k < 4; k++) {
        float h = fmaf(r[k], sc[base + col + k], sh[base + col + k]);
        r[k] = (h >= 0.f) ? h : 0.01f * h;
    }
    *(float4*)(out + i) = make_float4(r[0], r[1], r[2], r[3]);
}

// ---------------- launch ----------------
extern "C" void kernel_launch(void* const* d_in, const int* in_sizes, int n_in,
                              void* d_out, int out_size) {
    const float* x_user  = (const float*)d_in[0];
    const float* x_item  = (const float*)d_in[1];
    const float* W1_user = (const float*)d_in[2];
    const float* W1_item = (const float*)d_in[4];
    const float* W2_user = (const float*)d_in[6];
    const float* W2_item = (const float*)d_in[8];
    const float* g_user  = (const float*)d_in[10];
    const float* be_user = (const float*)d_in[11];
    const float* g_item  = (const float*)d_in[12];
    const float* be_item = (const float*)d_in[13];

    const int Nu = in_sizes[0] / 64;
    const int Ni = in_sizes[1] / 128;
    float* out = (float*)d_out;

    __half* hbuf = nullptr;
    cudaGetSymbolAddress((void**)&hbuf, g_H);

    constexpr int SM_U = 65536 + 128 * (64 * 2 + 16) + 1024;    // 85 KB
    constexpr int SM_I = 65536 + 128 * (128 * 2 + 16) + 1024;   // 101 KB
    cudaFuncSetAttribute(gemm1_kernel<64, 0>,  cudaFuncAttributeMaxDynamicSharedMemorySize, SM_U);
    cudaFuncSetAttribute(gemm1_kernel<128, 1>, cudaFuncAttributeMaxDynamicSharedMemorySize, SM_I);

    zero_stats_kernel<<<1, 256>>>();
    fold_kernel<<<DO, 128>>>(W1_user, W2_user, 64, 0);
    fold_kernel<<<DO, 128>>>(W1_item, W2_item, 128, 1);

    const int tiles_u = (Nu + 127) / 128;
    const int tiles_i = (Ni + 127) / 128;
    const int GRID = 296;

    gemm1_kernel<64, 0><<<(tiles_u < GRID ? tiles_u : GRID), 256, SM_U>>>(x_user, hbuf, Nu, tiles_u);
    gemm1_kernel<128, 1><<<(tiles_i < GRID ? tiles_i : GRID), 256, SM_I>>>(x_item, hbuf + (size_t)Nu * DO, Ni, tiles_i);

    finalize_kernel<<<1, 256>>>(g_user, be_user, g_item, be_item, 1.0f / (float)Nu, 1.0f / (float)Ni);

    long long total  = ((long long)Nu + (long long)Ni) * DO;
    long long total4 = total / 4;
    unsigned grid = (unsigned)((total4 + 255) / 256);
    norm_kernel<<<grid, 256>>>(hbuf, out, (long long)Nu * DO, total4);
}